// round 14
// baseline (speedup 1.0000x reference)
#include <cuda_runtime.h>

// tanhP1 bitstream stencil — final config: CH=32, float2, MLP=8 batched
// loads, store-only streaming hint, 128-thread blocks.
// out[t] = n5 * x[t-8]:
//   n1 = x[t]*x[t-4]
//   n2 = 1 - n1*c2[t]
//   n3 = 1 - n2*c3[t]*n1[t-1]
//   n4 = 1 - n3*c4[t]*n1[t-2]
//   n5 = 1 - n4*c5[t]*n1[t-3]
// Exact {0,1} floats -> FFMA arithmetic is bit-exact.
//
// Experiment map (R1-R13):
//   chunk count parabola: 1->5.55 TB/s, 4->6.11, 8->6.11 (best), 16->5.60
//   store-only __stcs: -5 MB DRAM-effective (L2 keeps x halo), -1.1 us
//   loads stay DEFAULT: main-loop rows ARE the next chunk's halo; .cs on
//     loads would evict them before the neighbor chunk reads them
//   occupancy >54%, grid order, scalar/float4 width, phase-sep: neutral/neg
//   at 80.1 us ncu vs 79.4 us = effective-bytes/achieved-BW floor
// This round: 128-thread blocks (finer allocation quantum / wave tail).

#define TT 256
#define CH 32          // chunk length; 8 concurrent chunks (proven optimum)

__global__ __launch_bounds__(128)
void tanhP1_kernel(const float2* __restrict__ x,
                   const float*  __restrict__ c2,
                   const float*  __restrict__ c3,
                   const float*  __restrict__ c4,
                   const float*  __restrict__ c5,
                   float2* __restrict__ out,
                   int n2)   // N/2 float2 columns
{
    __shared__ float4 cc[TT];
    for (int i = threadIdx.x; i < TT; i += blockDim.x)
        cc[i] = make_float4(c2[i], c3[i], c4[i], c5[i]);
    __syncthreads();

    const int col = blockIdx.x * blockDim.x + threadIdx.x;
    if (col >= n2) return;
    const int t0 = blockIdx.y * CH;          // multiple of 8

    const float2* xp = x + col;
    float2*       op = out + col;

    // Delay lines: x at time s lives in slot s&7; n1 at time s in slot s&3.
    float xh[8][2];
    float nh[4][2];

    if (t0 == 0) {
#pragma unroll
        for (int i = 0; i < 8; i++) { xh[i][0] = 0.0f; xh[i][1] = 0.0f; }
#pragma unroll
        for (int i = 0; i < 4; i++) { nh[i][0] = 0.0f; nh[i][1] = 0.0f; }
    } else {
        // Halo rows t0-8..t0-1 land in slots 0..7 (t0 % 8 == 0).
        float2 hv[8];
#pragma unroll
        for (int k = 0; k < 8; k++)
            hv[k] = xp[(long)(t0 - 8 + k) * n2];
#pragma unroll
        for (int k = 0; k < 8; k++) { xh[k][0] = hv[k].x; xh[k][1] = hv[k].y; }
        // n1[s] = x[s]*x[s-4] for s = t0-3..t0-1 -> slots 1,2,3.
#pragma unroll
        for (int l = 0; l < 2; l++) {
            nh[0][l] = 0.0f;                    // overwritten before first read
            nh[1][l] = xh[5][l] * xh[1][l];
            nh[2][l] = xh[6][l] * xh[2][l];
            nh[3][l] = xh[7][l] * xh[3][l];
        }
    }

    for (int tb = 0; tb < CH; tb += 8) {
        // ---- front-batch the 8 independent row loads (MLP = 8) ----
        float2 xv[8];
#pragma unroll
        for (int k = 0; k < 8; k++)
            xv[k] = xp[(long)(t0 + tb + k) * n2];

        // ---- compute + store the 8 rows ----
#pragma unroll
        for (int k = 0; k < 8; k++) {
            const int t = t0 + tb + k;       // t % 8 == k
            const float4 cv = cc[t];

            const int i8 = k;                // x[t-8] slot (then receives x[t])
            const int i4 = (k + 4) & 7;      // x[t-4]
            const int j0 = k & 3;            // n1[t] destination
            const int j1 = (k + 3) & 3;      // n1[t-1]
            const int j2 = (k + 2) & 3;      // n1[t-2]
            const int j3 = (k + 1) & 3;      // n1[t-3]

            float xt[2] = {xv[k].x, xv[k].y};
            float ov[2];
#pragma unroll
            for (int l = 0; l < 2; l++) {
                const float n1  = xt[l] * xh[i4][l];
                const float n2v = 1.0f - n1  * cv.x;
                const float n3  = 1.0f - n2v * (cv.y * nh[j1][l]);
                const float n4v = 1.0f - n3  * (cv.z * nh[j2][l]);
                const float n5  = 1.0f - n4v * (cv.w * nh[j3][l]);
                ov[l] = n5 * xh[i8][l];
                xh[i8][l] = xt[l];
                nh[j0][l] = n1;
            }
            __stcs(op + (long)t * n2, make_float2(ov[0], ov[1]));
        }
    }
}

extern "C" void kernel_launch(void* const* d_in, const int* in_sizes, int n_in,
                              void* d_out, int out_size)
{
    const float* x  = (const float*)d_in[0];
    const float* c2 = (const float*)d_in[1];
    const float* c3 = (const float*)d_in[2];
    const float* c4 = (const float*)d_in[3];
    const float* c5 = (const float*)d_in[4];

    const int T  = in_sizes[1];           // 256
    const int N  = in_sizes[0] / T;       // 262144
    const int n2 = N / 2;                 // float2 columns

    const int threads = 128;
    dim3 grid((n2 + threads - 1) / threads, T / CH);
    tanhP1_kernel<<<grid, threads>>>((const float2*)x, c2, c3, c4, c5,
                                     (float2*)d_out, n2);
}

// round 15
// speedup vs baseline: 1.0193x; 1.0193x over previous
#include <cuda_runtime.h>

// tanhP1 bitstream stencil — FINAL: CH=32, float2, 256-thr blocks, MLP=8
// batched loads, store-only streaming hint.
// out[t] = n5 * x[t-8]:
//   n1 = x[t]*x[t-4]
//   n2 = 1 - n1*c2[t]
//   n3 = 1 - n2*c3[t]*n1[t-1]
//   n4 = 1 - n3*c4[t]*n1[t-2]
//   n5 = 1 - n4*c5[t]*n1[t-3]
// Exact {0,1} floats -> FFMA arithmetic is bit-exact (rel_err == 0).
//
// Converged experiment map (R1-R14):
//   chunk count: 1->5.55 TB/s, 4->6.11, 8->6.11 (best wall), 16->5.60
//   block size: 256 > 128 (per-block overhead dominates finer quantum)
//   store-only __stcs: L2 keeps x halo resident; -5 MB effective, -1.1 us
//   loads default: main-loop rows ARE the neighbor chunk's halo
//   occupancy >44%, grid order, scalar/float4, phase-sep, MLP16: no gain
//   Result: 80.1 us ncu vs 79.4 us effective-bytes/achieved-BW floor
//   (485 MB @ 6.05 TB/s); achieved-BW ceiling ~6.1 TB/s hit by 3 configs.

#define TT 256
#define CH 32          // chunk length; 8 concurrent chunks (proven optimum)

__global__ __launch_bounds__(256)
void tanhP1_kernel(const float2* __restrict__ x,
                   const float*  __restrict__ c2,
                   const float*  __restrict__ c3,
                   const float*  __restrict__ c4,
                   const float*  __restrict__ c5,
                   float2* __restrict__ out,
                   int n2)   // N/2 float2 columns
{
    __shared__ float4 cc[TT];
    for (int i = threadIdx.x; i < TT; i += blockDim.x)
        cc[i] = make_float4(c2[i], c3[i], c4[i], c5[i]);
    __syncthreads();

    const int col = blockIdx.x * blockDim.x + threadIdx.x;
    if (col >= n2) return;
    const int t0 = blockIdx.y * CH;          // multiple of 8

    const float2* xp = x + col;
    float2*       op = out + col;

    // Delay lines: x at time s lives in slot s&7; n1 at time s in slot s&3.
    float xh[8][2];
    float nh[4][2];

    if (t0 == 0) {
#pragma unroll
        for (int i = 0; i < 8; i++) { xh[i][0] = 0.0f; xh[i][1] = 0.0f; }
#pragma unroll
        for (int i = 0; i < 4; i++) { nh[i][0] = 0.0f; nh[i][1] = 0.0f; }
    } else {
        // Halo rows t0-8..t0-1 land in slots 0..7 (t0 % 8 == 0).
        float2 hv[8];
#pragma unroll
        for (int k = 0; k < 8; k++)
            hv[k] = xp[(long)(t0 - 8 + k) * n2];
#pragma unroll
        for (int k = 0; k < 8; k++) { xh[k][0] = hv[k].x; xh[k][1] = hv[k].y; }
        // n1[s] = x[s]*x[s-4] for s = t0-3..t0-1 -> slots 1,2,3.
#pragma unroll
        for (int l = 0; l < 2; l++) {
            nh[0][l] = 0.0f;                    // overwritten before first read
            nh[1][l] = xh[5][l] * xh[1][l];
            nh[2][l] = xh[6][l] * xh[2][l];
            nh[3][l] = xh[7][l] * xh[3][l];
        }
    }

    for (int tb = 0; tb < CH; tb += 8) {
        // ---- front-batch the 8 independent row loads (MLP = 8) ----
        float2 xv[8];
#pragma unroll
        for (int k = 0; k < 8; k++)
            xv[k] = xp[(long)(t0 + tb + k) * n2];

        // ---- compute + store the 8 rows ----
#pragma unroll
        for (int k = 0; k < 8; k++) {
            const int t = t0 + tb + k;       // t % 8 == k
            const float4 cv = cc[t];

            const int i8 = k;                // x[t-8] slot (then receives x[t])
            const int i4 = (k + 4) & 7;      // x[t-4]
            const int j0 = k & 3;            // n1[t] destination
            const int j1 = (k + 3) & 3;      // n1[t-1]
            const int j2 = (k + 2) & 3;      // n1[t-2]
            const int j3 = (k + 1) & 3;      // n1[t-3]

            float xt[2] = {xv[k].x, xv[k].y};
            float ov[2];
#pragma unroll
            for (int l = 0; l < 2; l++) {
                const float n1  = xt[l] * xh[i4][l];
                const float n2v = 1.0f - n1  * cv.x;
                const float n3  = 1.0f - n2v * (cv.y * nh[j1][l]);
                const float n4v = 1.0f - n3  * (cv.z * nh[j2][l]);
                const float n5  = 1.0f - n4v * (cv.w * nh[j3][l]);
                ov[l] = n5 * xh[i8][l];
                xh[i8][l] = xt[l];
                nh[j0][l] = n1;
            }
            __stcs(op + (long)t * n2, make_float2(ov[0], ov[1]));
        }
    }
}

extern "C" void kernel_launch(void* const* d_in, const int* in_sizes, int n_in,
                              void* d_out, int out_size)
{
    const float* x  = (const float*)d_in[0];
    const float* c2 = (const float*)d_in[1];
    const float* c3 = (const float*)d_in[2];
    const float* c4 = (const float*)d_in[3];
    const float* c5 = (const float*)d_in[4];

    const int T  = in_sizes[1];           // 256
    const int N  = in_sizes[0] / T;       // 262144
    const int n2 = N / 2;                 // float2 columns

    const int threads = 256;
    dim3 grid((n2 + threads - 1) / threads, T / CH);
    tanhP1_kernel<<<grid, threads>>>((const float2*)x, c2, c3, c4, c5,
                                     (float2*)d_out, n2);
}